// round 1
// baseline (speedup 1.0000x reference)
#include <cuda_runtime.h>
#include <cstdint>

// RoIPooling (TF2 crop_and_resize bilinear, POOL=7)
// feature_map: (1, 256, 256, 512) float32 NHWC
// proposals:   (512, 4) int32  [x, y, w, h]
// output:      (512, 7, 7, 512) float32
//
// One CTA per (proposal, py, px): 512*49 = 25088 blocks, 128 threads.
// Thread t handles channels [4t, 4t+4) via float4: 4 coalesced 2KB corner
// loads + nested-lerp blend + 1 coalesced 2KB store.

#define POOL 7
#define FM_H 256
#define FM_W 256
#define FM_C 512
#define NPROP 512

__global__ __launch_bounds__(128, 8)
void roi_pool_kernel(const float* __restrict__ fm,
                     const int*   __restrict__ props,
                     float*       __restrict__ out)
{
    const int bid = blockIdx.x;           // 0 .. 25087
    const int n   = bid / (POOL * POOL);
    const int pos = bid - n * (POOL * POOL);
    const int py  = pos / POOL;
    const int px  = pos - py * POOL;

    // proposal box (aligned int4 load)
    const int4 box = reinterpret_cast<const int4*>(props)[n];
    const int bx = box.x, by = box.y, bw = box.z, bh = box.w;

    // --- y axis coords (match reference float32 math) ---
    const float hf = (float)bh;
    float sy = ((float)py + 0.5f) * (hf / (float)POOL) - 0.5f;
    sy = fminf(fmaxf(sy, 0.0f), hf - 1.0f);
    const int   iy0 = (int)floorf(sy);
    const int   iy1 = min(iy0 + 1, bh - 1);
    const float fy  = sy - (float)iy0;
    const int   y0  = by + iy0;
    const int   y1  = by + iy1;

    // --- x axis coords ---
    const float wf = (float)bw;
    float sx = ((float)px + 0.5f) * (wf / (float)POOL) - 0.5f;
    sx = fminf(fmaxf(sx, 0.0f), wf - 1.0f);
    const int   ix0 = (int)floorf(sx);
    const int   ix1 = min(ix0 + 1, bw - 1);
    const float fx  = sx - (float)ix0;
    const int   x0  = bx + ix0;
    const int   x1  = bx + ix1;

    // corner row-vector base pointers (each 2KB contiguous over channels)
    const float4* __restrict__ p00 =
        reinterpret_cast<const float4*>(fm + ((size_t)y0 * FM_W + x0) * FM_C);
    const float4* __restrict__ p01 =
        reinterpret_cast<const float4*>(fm + ((size_t)y0 * FM_W + x1) * FM_C);
    const float4* __restrict__ p10 =
        reinterpret_cast<const float4*>(fm + ((size_t)y1 * FM_W + x0) * FM_C);
    const float4* __restrict__ p11 =
        reinterpret_cast<const float4*>(fm + ((size_t)y1 * FM_W + x1) * FM_C);

    const int c = threadIdx.x;            // float4 index 0..127

    const float4 a = p00[c];
    const float4 b = p01[c];
    const float4 g = p10[c];
    const float4 d = p11[c];

    const float ofx = 1.0f - fx;
    const float ofy = 1.0f - fy;

    float4 o;
    {
        const float t0 = a.x * ofx + b.x * fx;
        const float t1 = g.x * ofx + d.x * fx;
        o.x = t0 * ofy + t1 * fy;
    }
    {
        const float t0 = a.y * ofx + b.y * fx;
        const float t1 = g.y * ofx + d.y * fx;
        o.y = t0 * ofy + t1 * fy;
    }
    {
        const float t0 = a.z * ofx + b.z * fx;
        const float t1 = g.z * ofx + d.z * fx;
        o.z = t0 * ofy + t1 * fy;
    }
    {
        const float t0 = a.w * ofx + b.w * fx;
        const float t1 = g.w * ofx + d.w * fx;
        o.w = t0 * ofy + t1 * fy;
    }

    reinterpret_cast<float4*>(out + (size_t)bid * FM_C)[c] = o;
}

extern "C" void kernel_launch(void* const* d_in, const int* in_sizes, int n_in,
                              void* d_out, int out_size)
{
    const float* fm    = (const float*)d_in[0];
    const int*   props = (const int*)d_in[1];
    float*       out   = (float*)d_out;

    const int blocks = NPROP * POOL * POOL;   // 25088
    roi_pool_kernel<<<blocks, 128>>>(fm, props, out);
}

// round 2
// speedup vs baseline: 1.1569x; 1.1569x over previous
#include <cuda_runtime.h>
#include <cstdint>

// RoIPooling (TF2 crop_and_resize bilinear, POOL=7)
// feature_map: (1, 256, 256, 512) float32 NHWC
// proposals:   (512, 4) int32  [x, y, w, h]
// output:      (512, 7, 7, 512) float32
//
// R2: One CTA per (proposal, py): 512*7 = 3584 blocks, 128 threads.
// Each thread owns channel-quad c and iterates the 7 px cells (unrolled):
// 28 independent corner loads in flight (high MLP), corners drawn from
// <=16 distinct pixels in 2 rows (L1-resident), streaming stores for the
// write-once output.

#define POOL 7
#define FM_H 256
#define FM_W 256
#define FM_C 512
#define NPROP 512

__global__ __launch_bounds__(128)
void roi_pool_kernel(const float* __restrict__ fm,
                     const int*   __restrict__ props,
                     float*       __restrict__ out)
{
    const int bid = blockIdx.x;           // 0 .. 3583
    const int n   = bid / POOL;
    const int py  = bid - n * POOL;

    // proposal box (aligned int4 load)
    const int4 box = reinterpret_cast<const int4*>(props)[n];
    const int bx = box.x, by = box.y, bw = box.z, bh = box.w;

    // --- y axis coords (match reference float32 math) ---
    const float hf = (float)bh;
    float sy = ((float)py + 0.5f) * (hf / (float)POOL) - 0.5f;
    sy = fminf(fmaxf(sy, 0.0f), hf - 1.0f);
    const int   iy0 = (int)floorf(sy);
    const int   iy1 = min(iy0 + 1, bh - 1);
    const float fy  = sy - (float)iy0;
    const float ofy = 1.0f - fy;

    const float4* __restrict__ row0 =
        reinterpret_cast<const float4*>(fm + ((size_t)(by + iy0) * FM_W + bx) * FM_C);
    const float4* __restrict__ row1 =
        reinterpret_cast<const float4*>(fm + ((size_t)(by + iy1) * FM_W + bx) * FM_C);

    const int c = threadIdx.x;            // float4 (channel-quad) index 0..127
    const float wf = (float)bw;
    const float xscale = wf / (float)POOL;

    float4* __restrict__ orow =
        reinterpret_cast<float4*>(out + ((size_t)n * (POOL * POOL) + (size_t)py * POOL) * FM_C);

    #pragma unroll
    for (int px = 0; px < POOL; ++px) {
        // --- x axis coords ---
        float sx = ((float)px + 0.5f) * xscale - 0.5f;
        sx = fminf(fmaxf(sx, 0.0f), wf - 1.0f);
        const int   ix0 = (int)floorf(sx);
        const int   ix1 = min(ix0 + 1, bw - 1);
        const float fx  = sx - (float)ix0;
        const float ofx = 1.0f - fx;

        const float4 a = row0[(size_t)ix0 * (FM_C / 4) + c];
        const float4 b = row0[(size_t)ix1 * (FM_C / 4) + c];
        const float4 g = row1[(size_t)ix0 * (FM_C / 4) + c];
        const float4 d = row1[(size_t)ix1 * (FM_C / 4) + c];

        float4 o;
        o.x = (a.x * ofx + b.x * fx) * ofy + (g.x * ofx + d.x * fx) * fy;
        o.y = (a.y * ofx + b.y * fx) * ofy + (g.y * ofx + d.y * fx) * fy;
        o.z = (a.z * ofx + b.z * fx) * ofy + (g.z * ofx + d.z * fx) * fy;
        o.w = (a.w * ofx + b.w * fx) * ofy + (g.w * ofx + d.w * fx) * fy;

        // streaming store: output is write-once, keep it out of L2's way
        __stcs(&orow[(size_t)px * (FM_C / 4) + c], o);
    }
}

extern "C" void kernel_launch(void* const* d_in, const int* in_sizes, int n_in,
                              void* d_out, int out_size)
{
    const float* fm    = (const float*)d_in[0];
    const int*   props = (const int*)d_in[1];
    float*       out   = (float*)d_out;

    const int blocks = NPROP * POOL;      // 3584
    roi_pool_kernel<<<blocks, 128>>>(fm, props, out);
}